// round 10
// baseline (speedup 1.0000x reference)
#include <cuda_runtime.h>
#include <cstdint>

// Problem constants (fixed shapes per reference)
#define NTOK  (32 * 8192)   // 262144 tokens
#define DIM   256           // K
#define NEXP  16
#define POUT  64            // N
#define BM    128           // tokens per tile
#define CK    64            // K per chunk
#define NCH   (DIM / CK)    // 4 chunks

// ---------------- scratch ----------------
__device__ int g_sorted[NEXP][NTOK];   // per-expert slot regions
__device__ int g_cursor[NEXP];
// Pre-transposed + tf32-rounded W: [e][c][half][n(64)][k(32)] fp32,
// sw128-swizzled 128-B rows, stored as raw bytes (16 KB per (e,c)).
__device__ unsigned char g_Wt[NEXP][NCH][16384];

// ---------------- helpers ----------------
__device__ __forceinline__ uint32_t s2u(const void* p) {
    uint32_t a;
    asm("{ .reg .u64 t; cvta.to.shared.u64 t, %1; cvt.u32.u64 %0, t; }" : "=r"(a) : "l"(p));
    return a;
}
__device__ __forceinline__ uint32_t sw128(uint32_t o) { return o ^ ((o >> 3) & 0x70); }

__device__ __forceinline__ uint32_t f2tf(float f) {
    uint32_t r;
    asm("cvt.rna.tf32.f32 %0, %1;" : "=r"(r) : "f"(f));
    return r;
}
__device__ __forceinline__ void ldsm_x4(uint32_t addr, uint32_t r[4]) {
    asm volatile("ldmatrix.sync.aligned.m8n8.x4.shared.b16 {%0,%1,%2,%3}, [%4];"
                 : "=r"(r[0]), "=r"(r[1]), "=r"(r[2]), "=r"(r[3]) : "r"(addr));
}
__device__ __forceinline__ void mma1688(float c[4], const uint32_t a[4],
                                        uint32_t b0, uint32_t b1) {
    asm volatile(
        "mma.sync.aligned.m16n8k8.row.col.f32.tf32.tf32.f32 "
        "{%0,%1,%2,%3}, {%4,%5,%6,%7}, {%8,%9}, {%0,%1,%2,%3};"
        : "+f"(c[0]), "+f"(c[1]), "+f"(c[2]), "+f"(c[3])
        : "r"(a[0]), "r"(a[1]), "r"(a[2]), "r"(a[3]), "r"(b0), "r"(b1));
}
__device__ __forceinline__ void cpasync16(uint32_t dst, const void* src) {
    asm volatile("cp.async.cg.shared.global [%0], [%1], 16;"
                 :: "r"(dst), "l"(src) : "memory");
}

// ---------------- prep: W transpose + tf32 round + cursor zero ------------
__global__ void k_prep(const float* __restrict__ W) {
    if (blockIdx.x == 0 && threadIdx.x < NEXP) g_cursor[threadIdx.x] = 0;
    int e = blockIdx.x >> 2;
    int c = blockIdx.x & 3;
    int tid = threadIdx.x;
    __shared__ float sm[64 * 65];
    // load W chunk [64 k][64 n] (coalesced in n)
#pragma unroll
    for (int j = 0; j < 16; j++) {
        int v = tid + j * 256;
        int k = v >> 6, n = v & 63;
        sm[k * 65 + n] = W[((size_t)e * DIM + c * CK + k) * POUT + n];
    }
    __syncthreads();
    // write Bt [half][n][32 k] swizzled, tf32-rounded
#pragma unroll
    for (int j = 0; j < 4; j++) {
        int v = tid + j * 256;          // 0..1023 float4s
        int h = v >> 9;                 // k half
        int n = (v >> 3) & 63;
        int k4 = v & 7;                 // float4 within 32-k row
        uint4 o;
        o.x = f2tf(sm[(h * 32 + k4 * 4 + 0) * 65 + n]);
        o.y = f2tf(sm[(h * 32 + k4 * 4 + 1) * 65 + n]);
        o.z = f2tf(sm[(h * 32 + k4 * 4 + 2) * 65 + n]);
        o.w = f2tf(sm[(h * 32 + k4 * 4 + 3) * 65 + n]);
        *(uint4*)(g_Wt[e][c] + h * 8192 + sw128((uint32_t)(n * 128 + k4 * 16))) = o;
    }
}

// ---------------- direct scatter (order within expert is free) ----------------
__global__ void k_scatter(const int* __restrict__ idx) {
    __shared__ int sc[NEXP];
    __shared__ int sbase[NEXP];
    int t = threadIdx.x;
    int lane = t & 31;
    if (t < NEXP) sc[t] = 0;
    __syncthreads();
    int i = blockIdx.x * blockDim.x + t;
    int e = idx[i];
    unsigned mask = __match_any_sync(0xffffffffu, e);
    int leader = __ffs(mask) - 1;
    int base = 0;
    if (lane == leader) base = atomicAdd(&sc[e], __popc(mask));
    base = __shfl_sync(0xffffffffu, base, leader);
    int local = base + __popc(mask & ((1u << lane) - 1u));
    __syncthreads();
    if (t < NEXP && sc[t] > 0) sbase[t] = atomicAdd(&g_cursor[t], sc[t]);
    __syncthreads();
    g_sorted[e][sbase[e] + local] = i;
}

// ---------------- smem layout ----------------
// [0:256)    bias (64 f32)
// [256:768)  rows (128 int)
// [1024:)    2 x { A0 16K | A1 16K | B0 8K | B1 8K }  (2 x 48 KB)
//            A half h: 128 m-rows x 32 k fp32 (128-B rows, sw128)
//            B half h: 64 n-rows x 32 k fp32 (128-B rows, sw128)
// epilogue:  C tile (128 x 68 f32 = 34.8 KB) overlays buffer 0
#define SM_BIAS 0
#define SM_ROWS 256
#define SM_BUF  1024
#define STAGE   49152
#define SMEM_TOTAL (SM_BUF + 2 * STAGE)   // 99328
#define CS_STRIDE 68

// ---------------- grouped GEMM: tf32 single-pass, warp = m32 x n32 ---------
__global__ void __launch_bounds__(256, 2)
k_gemm_mma(const float* __restrict__ x, const float* __restrict__ bias,
           float* __restrict__ out) {
    // tile -> (expert, m0) via local prefix over final cursors (= counts)
    int tile = blockIdx.x;
    int e = -1, m0 = 0, accT = 0;
#pragma unroll
    for (int i = 0; i < NEXP; i++) {
        int cnt_i = g_cursor[i];
        int nt = (cnt_i + BM - 1) / BM;
        if (e < 0 && tile < accT + nt) { e = i; m0 = (tile - accT) * BM; }
        accT += nt;
    }
    if (e < 0) return;
    int cnt = g_cursor[e];

    extern __shared__ char smem[];
    uint32_t sb = s2u(smem);
    float* bias_s = (float*)(smem + SM_BIAS);
    int*   rows   = (int*)(smem + SM_ROWS);

    int tid = threadIdx.x;
    int wid = tid >> 5, L = tid & 31;

    if (tid < BM) {
        int m = m0 + tid;
        rows[tid] = (m < cnt) ? g_sorted[e][m] : -1;
    }
    if (tid < 16)
        *(float4*)(bias_s + tid * 4) = *(const float4*)(bias + e * POUT + tid * 4);
    __syncthreads();

    // per-thread A-load coords
    const int am = tid >> 4;            // m sub-row (8 rows at +16 stride)
    const int aq = tid & 15;            // float4 index within 64-float k chunk

    // warp tile: m32 x n32  (warp grid 4 x 2 over 128 x 64)
    const int mrow  = (wid & 3) * 32;
    const int nbase = (wid >> 2) * 32;

    // ldmatrix lane components (shared by A and B x4 loads)
    const int lrow = (L & 7) + ((L >> 3) & 1) * 8;   // row within 16-row tile pair
    const int lcol = (L >> 4) * 16;                  // byte col: 0 or 16 (+4 fp32)

    float acc[2][4][4];                  // [m16 frag][n8 group][4]
#pragma unroll
    for (int a = 0; a < 2; a++)
#pragma unroll
        for (int j = 0; j < 4; j++)
#pragma unroll
            for (int q = 0; q < 4; q++) acc[a][j][q] = 0.f;

    auto ldg_chunk = [&](int k0, float4 fa[8]) {
#pragma unroll
        for (int i = 0; i < 8; i++) {
            int m = am + i * 16;
            int row = rows[m];
            fa[i] = make_float4(0.f, 0.f, 0.f, 0.f);
            if (row >= 0) fa[i] = *(const float4*)(x + (size_t)row * DIM + k0 + aq * 4);
        }
    };
    auto sts_chunk = [&](const float4 fa[8], uint32_t bufOff) {
        uint32_t hbase = bufOff + (uint32_t)(aq >> 3) * 16384;  // k half
        uint32_t coff  = (uint32_t)((aq & 7) * 16);
#pragma unroll
        for (int i = 0; i < 8; i++) {
            int m = am + i * 16;
            uint4 o;
            o.x = f2tf(fa[i].x); o.y = f2tf(fa[i].y);
            o.z = f2tf(fa[i].z); o.w = f2tf(fa[i].w);
            *(uint4*)(smem + hbase + sw128((uint32_t)(m * 128) + coff)) = o;
        }
    };
    auto cp_b = [&](int c, uint32_t bufOff) {
        uint32_t bd = sb + bufOff + 32768;
        const unsigned char* src = g_Wt[e][c];
#pragma unroll
        for (int i = 0; i < 4; i++) {
            uint32_t o = (uint32_t)(tid + i * 256) * 16;   // 16 KB total
            cpasync16(bd + o, src + o);
        }
        asm volatile("cp.async.commit_group;" ::: "memory");
    };

    // ---- prologue: stage chunk 0 into buffer 0 ----
    float4 fa[8];
    cp_b(0, SM_BUF);
    ldg_chunk(0, fa);
    sts_chunk(fa, SM_BUF);
    asm volatile("cp.async.wait_group 0;" ::: "memory");
    __syncthreads();

    for (int c = 0; c < NCH; c++) {
        uint32_t buf  = SM_BUF + (uint32_t)(c & 1) * STAGE;
        uint32_t nbuf = SM_BUF + (uint32_t)((c + 1) & 1) * STAGE;
        const uint32_t A0 = sb + buf;            // A halves at +0, +16384
        const uint32_t B0 = sb + buf + 32768;    // B halves at +0, +8192

        if (c + 1 < NCH) {
            cp_b(c + 1, nbuf);
            ldg_chunk((c + 1) * CK, fa);
        }

        // ---- MMA phase: 8 k8-steps, 8 MMAs each ----
#pragma unroll
        for (int s = 0; s < 8; s++) {
            uint32_t Ah = A0 + (uint32_t)(s >> 2) * 16384;
            uint32_t Bh = B0 + (uint32_t)(s >> 2) * 8192;
            uint32_t cb = (uint32_t)((s & 3) * 32 + lcol);
            uint32_t av[2][4], bv[2][4];
#pragma unroll
            for (int a = 0; a < 2; a++)
                ldsm_x4(Ah + sw128((uint32_t)((mrow + a * 16 + lrow) * 128) + cb), av[a]);
#pragma unroll
            for (int g = 0; g < 2; g++)
                ldsm_x4(Bh + sw128((uint32_t)((nbase + g * 16 + lrow) * 128) + cb), bv[g]);
            // 8 MMAs, 8 independent acc chains
#pragma unroll
            for (int a = 0; a < 2; a++)
#pragma unroll
                for (int j = 0; j < 4; j++)
                    mma1688(acc[a][j], av[a], bv[j >> 1][j & 1], bv[j >> 1][2 + (j & 1)]);
        }

        // ---- stage next chunk's A into other buffer (overlaps others' MMA) ----
        if (c + 1 < NCH) {
            sts_chunk(fa, nbuf);
            asm volatile("cp.async.wait_group 0;" ::: "memory");
        }
        __syncthreads();
    }

    // ---- epilogue: transpose through smem, coalesced scatter ----
    float* Cs = (float*)(smem + SM_BUF);
#pragma unroll
    for (int a = 0; a < 2; a++) {
        int r = mrow + a * 16 + (L >> 2);
        int cbase = nbase + (L & 3) * 2;
#pragma unroll
        for (int j = 0; j < 4; j++) {
            int cc = cbase + j * 8;
            *(float2*)(Cs + r * CS_STRIDE + cc)       = make_float2(acc[a][j][0], acc[a][j][1]);
            *(float2*)(Cs + (r + 8) * CS_STRIDE + cc) = make_float2(acc[a][j][2], acc[a][j][3]);
        }
    }
    __syncthreads();
    {
        int r = tid >> 1;
        int half = tid & 1;
        int row = rows[r];
        if (row >= 0) {
            float* op = out + (size_t)row * POUT;
#pragma unroll
            for (int q = 0; q < 8; q++) {
                int c4 = half * 8 + q;
                float4 v = *(float4*)(Cs + r * CS_STRIDE + c4 * 4);
                float4 bv = *(float4*)(bias_s + c4 * 4);
                v.x += bv.x; v.y += bv.y; v.z += bv.z; v.w += bv.w;
                *(float4*)(op + c4 * 4) = v;
            }
        }
    }
}

// ---------------- launch ----------------
extern "C" void kernel_launch(void* const* d_in, const int* in_sizes, int n_in,
                              void* d_out, int out_size) {
    const float* x   = (const float*)d_in[0];  // [32,8192,256]
    const float* W   = (const float*)d_in[1];  // [16,256,64]
    const float* b   = (const float*)d_in[2];  // [16,64]
    const int*   idx = (const int*)d_in[3];    // [32,8192]
    float* out = (float*)d_out;                // [32,8192,64]

    cudaFuncSetAttribute(k_gemm_mma, cudaFuncAttributeMaxDynamicSharedMemorySize, SMEM_TOTAL);

    k_prep<<<NEXP * NCH, 256>>>(W);
    k_scatter<<<NTOK / 256, 256>>>(idx);

    int max_tiles = NTOK / BM + NEXP;
    k_gemm_mma<<<max_tiles, 256, SMEM_TOTAL>>>(x, b, out);
}

// round 12
// speedup vs baseline: 1.5310x; 1.5310x over previous
#include <cuda_runtime.h>
#include <cstdint>

// Problem constants (fixed shapes per reference)
#define NTOK  (32 * 8192)   // 262144 tokens
#define DIM   256           // K
#define NEXP  16
#define POUT  64            // N
#define BM    128           // tokens per tile
#define CK    64            // K per chunk
#define NCH   (DIM / CK)    // 4 chunks

// ---------------- scratch ----------------
__device__ int g_sorted[NEXP][NTOK];   // per-expert slot regions
__device__ int g_cursor[NEXP];
// Pre-split W tiles: fp16 hi at +0 (8 KB), fp16 lo*2048 at +8192 (8 KB),
// both in sw128-swizzled tile byte order ([k-row][n] 128-B rows).
__device__ unsigned char g_Wsp[NEXP][NCH][16384];

// ---------------- helpers ----------------
__device__ __forceinline__ uint32_t s2u(const void* p) {
    uint32_t a;
    asm("{ .reg .u64 t; cvta.to.shared.u64 t, %1; cvt.u32.u64 %0, t; }" : "=r"(a) : "l"(p));
    return a;
}
__device__ __forceinline__ uint32_t sw128(uint32_t o) { return o ^ ((o >> 3) & 0x70); }

// pack two fp32 into fp16x2 (rn)
__device__ __forceinline__ uint32_t f2h2(float lo, float hi) {
    uint32_t r;
    asm("cvt.rn.f16x2.f32 %0, %1, %2;" : "=r"(r) : "f"(hi), "f"(lo));
    return r;
}
// unpack fp16x2 -> two fp32
__device__ __forceinline__ void h22f2(uint32_t h, float& lo, float& hi) {
    asm("{ .reg .f16 a, b;\n\t"
        "mov.b32 {a, b}, %2;\n\t"
        "cvt.f32.f16 %0, a;\n\t"
        "cvt.f32.f16 %1, b; }"
        : "=f"(lo), "=f"(hi) : "r"(h));
}

__device__ __forceinline__ void ldsm_x4(uint32_t addr, uint32_t r[4]) {
    asm volatile("ldmatrix.sync.aligned.m8n8.x4.shared.b16 {%0,%1,%2,%3}, [%4];"
                 : "=r"(r[0]), "=r"(r[1]), "=r"(r[2]), "=r"(r[3]) : "r"(addr));
}
__device__ __forceinline__ void ldsm_x4_t(uint32_t addr, uint32_t r[4]) {
    asm volatile("ldmatrix.sync.aligned.m8n8.x4.trans.shared.b16 {%0,%1,%2,%3}, [%4];"
                 : "=r"(r[0]), "=r"(r[1]), "=r"(r[2]), "=r"(r[3]) : "r"(addr));
}
__device__ __forceinline__ void mma16816h(float c[4], const uint32_t a[4],
                                          uint32_t b0, uint32_t b1) {
    asm volatile(
        "mma.sync.aligned.m16n8k16.row.col.f32.f16.f16.f32 "
        "{%0,%1,%2,%3}, {%4,%5,%6,%7}, {%8,%9}, {%0,%1,%2,%3};"
        : "+f"(c[0]), "+f"(c[1]), "+f"(c[2]), "+f"(c[3])
        : "r"(a[0]), "r"(a[1]), "r"(a[2]), "r"(a[3]), "r"(b0), "r"(b1));
}
__device__ __forceinline__ void cpasync16(uint32_t dst, const void* src) {
    asm volatile("cp.async.cg.shared.global [%0], [%1], 16;"
                 :: "r"(dst), "l"(src) : "memory");
}

// ---------------- prep: W fp16 2-term split + cursor zero -----------------
__global__ void k_prep(const float* __restrict__ W) {
    if (blockIdx.x == 0 && threadIdx.x < NEXP) g_cursor[threadIdx.x] = 0;
    int e = blockIdx.x >> 2;
    int c = blockIdx.x & 3;
    int tid = threadIdx.x;
    const float* Wc = W + ((size_t)e * DIM + c * CK) * POUT;
#pragma unroll
    for (int i = 0; i < 4; i++) {
        int v = tid + i * 256;          // 0..1023 float4s over [64 k][16 n4]
        int kr = v >> 4, nq = v & 15;
        float4 f = *(const float4*)(Wc + (size_t)kr * POUT + nq * 4);
        uint32_t h01 = f2h2(f.x, f.y);
        uint32_t h23 = f2h2(f.z, f.w);
        float rx, ry, rz, rw;
        h22f2(h01, rx, ry);
        h22f2(h23, rz, rw);
        uint32_t l01 = f2h2((f.x - rx) * 2048.f, (f.y - ry) * 2048.f);
        uint32_t l23 = f2h2((f.z - rz) * 2048.f, (f.w - rw) * 2048.f);
        uint32_t off = sw128((uint32_t)(kr * 128 + nq * 8));
        uint2 hv, lv;
        hv.x = h01; hv.y = h23;
        lv.x = l01; lv.y = l23;
        *(uint2*)(g_Wsp[e][c] + off) = hv;
        *(uint2*)(g_Wsp[e][c] + 8192 + off) = lv;
    }
}

// ---------------- direct scatter (order within expert is free) ----------------
__global__ void k_scatter(const int* __restrict__ idx) {
    __shared__ int sc[NEXP];
    __shared__ int sbase[NEXP];
    int t = threadIdx.x;
    int lane = t & 31;
    if (t < NEXP) sc[t] = 0;
    __syncthreads();
    int i = blockIdx.x * blockDim.x + t;
    int e = idx[i];
    unsigned mask = __match_any_sync(0xffffffffu, e);
    int leader = __ffs(mask) - 1;
    int base = 0;
    if (lane == leader) base = atomicAdd(&sc[e], __popc(mask));
    base = __shfl_sync(0xffffffffu, base, leader);
    int local = base + __popc(mask & ((1u << lane) - 1u));
    __syncthreads();
    if (t < NEXP && sc[t] > 0) sbase[t] = atomicAdd(&g_cursor[t], sc[t]);
    __syncthreads();
    g_sorted[e][sbase[e] + local] = i;
}

// ---------------- smem layout ----------------
// [0:256)    bias (64 f32)
// [256:768)  rows (128 int)
// [1024:)    2 x { A 16K | B_hi 8K | B_lo 8K }  (2 x 32 KB)
// epilogue:  C tile (128 x 68 f32 = 34.8 KB) overlays buffers
#define SM_BIAS 0
#define SM_ROWS 256
#define SM_BUF  1024
#define STAGE   32768
#define SMEM_TOTAL (SM_BUF + 2 * STAGE)   // 66560
#define CS_STRIDE 68

// ---------------- grouped GEMM: fp16 2-term, warp = m32 x n32, 2 CTA/SM ----
__global__ void __launch_bounds__(256, 2)
k_gemm_mma(const float* __restrict__ x, const float* __restrict__ bias,
           float* __restrict__ out) {
    // tile -> (expert, m0) via local prefix over final cursors (= counts)
    int tile = blockIdx.x;
    int e = -1, m0 = 0, accT = 0;
#pragma unroll
    for (int i = 0; i < NEXP; i++) {
        int cnt_i = g_cursor[i];
        int nt = (cnt_i + BM - 1) / BM;
        if (e < 0 && tile < accT + nt) { e = i; m0 = (tile - accT) * BM; }
        accT += nt;
    }
    if (e < 0) return;
    int cnt = g_cursor[e];

    extern __shared__ char smem[];
    uint32_t sb = s2u(smem);
    float* bias_s = (float*)(smem + SM_BIAS);
    int*   rows   = (int*)(smem + SM_ROWS);

    int tid = threadIdx.x;
    int wid = tid >> 5, L = tid & 31;

    if (tid < BM) {
        int m = m0 + tid;
        rows[tid] = (m < cnt) ? g_sorted[e][m] : -1;
    }
    if (tid < 16)
        *(float4*)(bias_s + tid * 4) = *(const float4*)(bias + e * POUT + tid * 4);
    __syncthreads();

    // per-thread A-load coords
    const int am = tid >> 4;            // m sub-row (8 rows at +16 stride)
    const int aq = tid & 15;            // float4 index within 64-float k chunk

    // warp tile: m32 x n32  (warp grid 4 x 2 over 128 x 64)
    const int mrow  = (wid & 3) * 32;
    const int nbase = (wid >> 2) * 32;

    // ldmatrix lane-address components (pre-swizzle)
    int arow = (L & 15);                 // + mrow + a*16
    int acol = (L >> 4) * 8;             // fp16 elems, + s*16
    int brow = (L & 7) + ((L >> 3) & 1) * 8;
    int bcol = (L >> 4) * 8;             // + nbase + p*16

    float accH[2][4][4], accL[2][4][4];
#pragma unroll
    for (int a = 0; a < 2; a++)
#pragma unroll
        for (int j = 0; j < 4; j++)
#pragma unroll
            for (int q = 0; q < 4; q++) { accH[a][j][q] = 0.f; accL[a][j][q] = 0.f; }

    // A loader: LDG fp32, convert to packed fp16x2 in-register
    auto ldg_chunk = [&](int k0, uint2 ha[8]) {
#pragma unroll
        for (int i = 0; i < 8; i++) {
            int m = am + i * 16;
            int row = rows[m];
            float4 f = make_float4(0.f, 0.f, 0.f, 0.f);
            if (row >= 0) f = *(const float4*)(x + (size_t)row * DIM + k0 + aq * 4);
            ha[i].x = f2h2(f.x, f.y);
            ha[i].y = f2h2(f.z, f.w);
        }
    };
    auto sts_chunk = [&](const uint2 ha[8], uint32_t bufOff) {
#pragma unroll
        for (int i = 0; i < 8; i++) {
            int m = am + i * 16;
            *(uint2*)(smem + bufOff + sw128((uint32_t)(m * 128 + aq * 8))) = ha[i];
        }
    };
    auto cp_b = [&](int c, uint32_t bufOff) {
        uint32_t bd = sb + bufOff + 16384;
        const unsigned char* src = g_Wsp[e][c];
#pragma unroll
        for (int i = 0; i < 4; i++) {
            uint32_t o = (uint32_t)(tid + i * 256) * 16;   // 16 KB total (hi+lo)
            cpasync16(bd + o, src + o);
        }
        asm volatile("cp.async.commit_group;" ::: "memory");
    };

    // ---- prologue: stage chunk 0 into buffer 0 ----
    uint2 ha[8];
    cp_b(0, SM_BUF);
    ldg_chunk(0, ha);
    sts_chunk(ha, SM_BUF);
    asm volatile("cp.async.wait_group 0;" ::: "memory");
    __syncthreads();

    for (int c = 0; c < NCH; c++) {
        uint32_t buf  = SM_BUF + (uint32_t)(c & 1) * STAGE;
        uint32_t nbuf = SM_BUF + (uint32_t)((c + 1) & 1) * STAGE;
        const uint32_t A0  = sb + buf;
        const uint32_t BHI = A0 + 16384, BLO = A0 + 24576;

        if (c + 1 < NCH) {
            cp_b(c + 1, nbuf);
            ldg_chunk((c + 1) * CK, ha);
        }

        // ---- MMA phase: warp m32 x n32, 2 terms ----
#pragma unroll
        for (int s = 0; s < 4; s++) {
            uint32_t av[2][4];
#pragma unroll
            for (int a = 0; a < 2; a++)
                ldsm_x4(A0 + sw128((uint32_t)((mrow + a * 16 + arow) * 128
                                              + (s * 16 + acol) * 2)), av[a]);
            uint32_t bh[2][4], bl[2][4];
#pragma unroll
            for (int p = 0; p < 2; p++) {
                uint32_t boff = sw128((uint32_t)((s * 16 + brow) * 128
                                                 + (nbase + p * 16 + bcol) * 2));
                ldsm_x4_t(BHI + boff, bh[p]);
                ldsm_x4_t(BLO + boff, bl[p]);
            }
            // 16 MMAs, 16 distinct acc chains
#pragma unroll
            for (int a = 0; a < 2; a++)
#pragma unroll
                for (int p = 0; p < 2; p++) {
                    mma16816h(accH[a][2 * p],     av[a], bh[p][0], bh[p][1]);
                    mma16816h(accH[a][2 * p + 1], av[a], bh[p][2], bh[p][3]);
                    mma16816h(accL[a][2 * p],     av[a], bl[p][0], bl[p][1]);
                    mma16816h(accL[a][2 * p + 1], av[a], bl[p][2], bl[p][3]);
                }
        }

        // ---- stage next chunk's A into other buffer (overlaps others' MMA) ----
        if (c + 1 < NCH) {
            sts_chunk(ha, nbuf);
            asm volatile("cp.async.wait_group 0;" ::: "memory");
        }
        __syncthreads();
    }

    // ---- merge lo term, epilogue: transpose through smem, coalesced scatter ----
    const float LS = 1.0f / 2048.0f;
    float* Cs = (float*)(smem + SM_BUF);
#pragma unroll
    for (int a = 0; a < 2; a++) {
        int r = mrow + a * 16 + (L >> 2);
        int cbase = nbase + (L & 3) * 2;
#pragma unroll
        for (int j = 0; j < 4; j++) {
            int cc = cbase + j * 8;
            *(float2*)(Cs + r * CS_STRIDE + cc) =
                make_float2(accH[a][j][0] + accL[a][j][0] * LS,
                            accH[a][j][1] + accL[a][j][1] * LS);
            *(float2*)(Cs + (r + 8) * CS_STRIDE + cc) =
                make_float2(accH[a][j][2] + accL[a][j][2] * LS,
                            accH[a][j][3] + accL[a][j][3] * LS);
        }
    }
    __syncthreads();
    {
        int r = tid >> 1;
        int half = tid & 1;
        int row = rows[r];
        if (row >= 0) {
            float* op = out + (size_t)row * POUT;
#pragma unroll
            for (int q = 0; q < 8; q++) {
                int c4 = half * 8 + q;
                float4 v = *(float4*)(Cs + r * CS_STRIDE + c4 * 4);
                float4 bv = *(float4*)(bias_s + c4 * 4);
                v.x += bv.x; v.y += bv.y; v.z += bv.z; v.w += bv.w;
                *(float4*)(op + c4 * 4) = v;
            }
        }
    }
}

// ---------------- launch ----------------
extern "C" void kernel_launch(void* const* d_in, const int* in_sizes, int n_in,
                              void* d_out, int out_size) {
    const float* x   = (const float*)d_in[0];  // [32,8192,256]
    const float* W   = (const float*)d_in[1];  // [16,256,64]
    const float* b   = (const float*)d_in[2];  // [16,64]
    const int*   idx = (const int*)d_in[3];    // [32,8192]
    float* out = (float*)d_out;                // [32,8192,64]

    cudaFuncSetAttribute(k_gemm_mma, cudaFuncAttributeMaxDynamicSharedMemorySize, SMEM_TOTAL);

    k_prep<<<NEXP * NCH, 256>>>(W);
    k_scatter<<<NTOK / 256, 256>>>(idx);

    int max_tiles = NTOK / BM + NEXP;
    k_gemm_mma<<<max_tiles, 256, SMEM_TOTAL>>>(x, b, out);
}